// round 8
// baseline (speedup 1.0000x reference)
#include <cuda_runtime.h>
#include <cuda_bf16.h>
#include <math.h>
#include <cstdint>
#include <string.h>

#define HID     2048
#define NHEADS  16
#define HDIM    128
#define BATCHSZ 2
#define SEQLEN  2048
#define MTOT    (BATCHSZ * SEQLEN)   // 4096

// ---------------- scratch (allocation-free), all bf16 split pairs ----------
__device__ __nv_bfloat16 g_xhi[MTOT * HID],  g_xlo[MTOT * HID];
__device__ __nv_bfloat16 g_whi[4 * HID * HID], g_wlo[4 * HID * HID];
__device__ __nv_bfloat16 g_qhi[MTOT * HID],  g_qlo[MTOT * HID];
__device__ __nv_bfloat16 g_khi[MTOT * HID],  g_klo[MTOT * HID];
__device__ __nv_bfloat16 g_vhi[MTOT * HID],  g_vlo[MTOT * HID];
__device__ __nv_bfloat16 g_ohi[MTOT * HID],  g_olo[MTOT * HID];

// ============================ helpers ======================================
__device__ __forceinline__ uint32_t smem_u32(const void* p) {
    uint32_t a;
    asm("{ .reg .u64 t; cvta.to.shared.u64 t, %1; cvt.u32.u64 %0, t; }"
        : "=r"(a) : "l"(p));
    return a;
}

#define LDSM_X4(r0, r1, r2, r3, addr)                                    \
    asm volatile("ldmatrix.sync.aligned.m8n8.x4.shared.b16 "             \
                 "{%0,%1,%2,%3}, [%4];"                                  \
                 : "=r"(r0), "=r"(r1), "=r"(r2), "=r"(r3) : "r"(addr))

#define LDSM_X4_T(r0, r1, r2, r3, addr)                                  \
    asm volatile("ldmatrix.sync.aligned.m8n8.x4.trans.shared.b16 "       \
                 "{%0,%1,%2,%3}, [%4];"                                  \
                 : "=r"(r0), "=r"(r1), "=r"(r2), "=r"(r3) : "r"(addr))

#define MMA_BF16(c0, c1, c2, c3, a0, a1, a2, a3, b0, b1)                 \
    asm volatile("mma.sync.aligned.m16n8k16.row.col.f32.bf16.bf16.f32 "  \
                 "{%0,%1,%2,%3}, {%4,%5,%6,%7}, {%8,%9}, {%0,%1,%2,%3};" \
                 : "+f"(c0), "+f"(c1), "+f"(c2), "+f"(c3)                \
                 : "r"(a0), "r"(a1), "r"(a2), "r"(a3), "r"(b0), "r"(b1))

#define CP16(saddr, gptr)                                                \
    asm volatile("cp.async.cg.shared.global [%0], [%1], 16;"             \
                 :: "r"(saddr), "l"(gptr))
#define CP_COMMIT() asm volatile("cp.async.commit_group;" ::: "memory")
#define CP_WAIT0()  asm volatile("cp.async.wait_group 0;" ::: "memory")
#define CP_WAIT1()  asm volatile("cp.async.wait_group 1;" ::: "memory")

__device__ __forceinline__ void split_bf16(float x, __nv_bfloat16& hi, __nv_bfloat16& lo) {
    hi = __float2bfloat16_rn(x);
    lo = __float2bfloat16_rn(x - __bfloat162float(hi));
}
__device__ __forceinline__ uint32_t packbf(__nv_bfloat16 a, __nv_bfloat16 b) {
    __nv_bfloat162 t; t.x = a; t.y = b;
    uint32_t u; memcpy(&u, &t, 4);
    return u;
}

// ======================= split kernels (one-time) ==========================
__global__ __launch_bounds__(256)
void split_f32_kernel(const float* __restrict__ src,
                      __nv_bfloat16* __restrict__ hi,
                      __nv_bfloat16* __restrict__ lo, int n) {
    const int i = (blockIdx.x * 256 + threadIdx.x) * 4;
    if (i >= n) return;
    float4 v = *(const float4*)(src + i);
    __nv_bfloat16 hx, lx, hy, ly;
    split_bf16(v.x, hx, lx); split_bf16(v.y, hy, ly);
    *(__nv_bfloat162*)(hi + i) = __nv_bfloat162(hx, hy);
    *(__nv_bfloat162*)(lo + i) = __nv_bfloat162(lx, ly);
    split_bf16(v.z, hx, lx); split_bf16(v.w, hy, ly);
    *(__nv_bfloat162*)(hi + i + 2) = __nv_bfloat162(hx, hy);
    *(__nv_bfloat162*)(lo + i + 2) = __nv_bfloat162(lx, ly);
}

// ================= pipelined bf16-split GEMM (cp.async, 3-stage) ===========
// C[M=4096, N=2048] = A @ W^T + bias, pre-split bf16 inputs.
// CTA 128x128, 256 threads = 8 warps (2M x 4N), warp tile 64x32.
// K chunk 32. 3-stage cp.async (prefetch distance 2). Term-major MMA order
// (hh, hl, lh over nf) -> dependent-acc spacing 4.
#define KSTRIDE 40
#define TILE_B  (128 * KSTRIDE * 2)      // 10240 B
#define STAGE_B (4 * TILE_B)             // 40960 B
#define GSM_TOTAL (3 * STAGE_B)          // 122880 B
#define NKC (HID / 32)                   // 64

// MODE 0: fp32 Out[m*HID+n].  MODE 1: bf16 split OutHi/OutLo [b,h,s,d] * scale
template <int MODE>
__device__ __forceinline__ void gemm_body(const __nv_bfloat16* __restrict__ Ahi,
                                          const __nv_bfloat16* __restrict__ Alo,
                                          const __nv_bfloat16* __restrict__ Whi,
                                          const __nv_bfloat16* __restrict__ Wlo,
                                          const float* __restrict__ Bias,
                                          float* __restrict__ OutF,
                                          __nv_bfloat16* __restrict__ OutHi,
                                          __nv_bfloat16* __restrict__ OutLo,
                                          float scale) {
    extern __shared__ char sm[];
    const uint32_t sb = smem_u32(sm);
    const int tid  = threadIdx.x;
    const int wid  = tid >> 5;
    const int lane = tid & 31;
    const int m0 = blockIdx.y * 128;
    const int n0 = blockIdx.x * 128;
    const int wm = wid & 1;
    const int wn = wid >> 1;

    const int lrow = (lane & 7) + ((lane >> 3) & 1) * 8;
    const int lk   = (lane >> 4) * 8;

    // loader: 256 threads, rows 0..63 (+64), 16B chunk = tid&3
    const int r0 = tid >> 2;                 // 0..63
    const int c0 = (tid & 3) * 8;            // bf16 col 0,8,16,24
    const __nv_bfloat16* gA[4];
    gA[0] = Ahi + (size_t)(m0 + r0) * HID + c0;
    gA[1] = Alo + (size_t)(m0 + r0) * HID + c0;
    gA[2] = Whi + (size_t)(n0 + r0) * HID + c0;
    gA[3] = Wlo + (size_t)(n0 + r0) * HID + c0;
    const uint32_t sA0 = sb + (uint32_t)(r0 * 80 + (tid & 3) * 16);
    const uint32_t sA1 = sA0 + 64 * 80;

    float acc[4][4][4];
#pragma unroll
    for (int i = 0; i < 4; i++)
#pragma unroll
        for (int j = 0; j < 4; j++)
#pragma unroll
            for (int c = 0; c < 4; c++) acc[i][j][c] = 0.f;

    // ---- prologue: stages 0,1 ----
#pragma unroll
    for (int s = 0; s < 2; s++) {
        const uint32_t so = (uint32_t)s * STAGE_B;
        const int go = s * 32;
#pragma unroll
        for (int t = 0; t < 4; t++) {
            CP16(sA0 + so + t * TILE_B, gA[t] + go);
            CP16(sA1 + so + t * TILE_B, gA[t] + (size_t)64 * HID + go);
        }
        CP_COMMIT();
    }

    int stg_idx = 0;
    for (int kc = 0; kc < NKC; kc++) {
        CP_WAIT1();
        __syncthreads();
        // prefetch kc+2 (empty commit keeps group arithmetic uniform)
        if (kc + 2 < NKC) {
            int pidx = stg_idx + 2; if (pidx >= 3) pidx -= 3;
            const uint32_t so = (uint32_t)pidx * STAGE_B;
            const int go = (kc + 2) * 32;
#pragma unroll
            for (int t = 0; t < 4; t++) {
                CP16(sA0 + so + t * TILE_B, gA[t] + go);
                CP16(sA1 + so + t * TILE_B, gA[t] + (size_t)64 * HID + go);
            }
        }
        CP_COMMIT();

        const uint32_t stg = (uint32_t)stg_idx * STAGE_B;
        stg_idx++; if (stg_idx == 3) stg_idx = 0;
        const uint32_t aH = sb + stg + (uint32_t)(((wm * 64 + lrow) * KSTRIDE + lk) * 2);
        const uint32_t bH = sb + stg + 2 * TILE_B +
                            (uint32_t)(((wn * 32 + lrow) * KSTRIDE + lk) * 2);
#pragma unroll
        for (int ks = 0; ks < 2; ks++) {
            const uint32_t ko = (uint32_t)(ks * 32);
            uint32_t bh[4][2], bl[4][2];
#pragma unroll
            for (int p = 0; p < 2; p++) {
                const uint32_t ba = bH + (uint32_t)(p * 16 * KSTRIDE * 2) + ko;
                uint32_t q0, q1, q2, q3;
                LDSM_X4(q0, q1, q2, q3, ba);
                bh[2 * p][0] = q0; bh[2 * p][1] = q2;
                bh[2 * p + 1][0] = q1; bh[2 * p + 1][1] = q3;
                LDSM_X4(q0, q1, q2, q3, ba + TILE_B);
                bl[2 * p][0] = q0; bl[2 * p][1] = q2;
                bl[2 * p + 1][0] = q1; bl[2 * p + 1][1] = q3;
            }
#pragma unroll
            for (int mf = 0; mf < 4; mf++) {
                const uint32_t aa = aH + (uint32_t)(mf * 16 * KSTRIDE * 2) + ko;
                uint32_t ah0, ah1, ah2, ah3, al0, al1, al2, al3;
                LDSM_X4(ah0, ah1, ah2, ah3, aa);
                LDSM_X4(al0, al1, al2, al3, aa + TILE_B);
                // term-major: all nf for hh, then hl, then lh (acc spacing 4)
#pragma unroll
                for (int nf = 0; nf < 4; nf++)
                    MMA_BF16(acc[mf][nf][0], acc[mf][nf][1], acc[mf][nf][2], acc[mf][nf][3],
                             ah0, ah1, ah2, ah3, bh[nf][0], bh[nf][1]);
#pragma unroll
                for (int nf = 0; nf < 4; nf++)
                    MMA_BF16(acc[mf][nf][0], acc[mf][nf][1], acc[mf][nf][2], acc[mf][nf][3],
                             ah0, ah1, ah2, ah3, bl[nf][0], bl[nf][1]);
#pragma unroll
                for (int nf = 0; nf < 4; nf++)
                    MMA_BF16(acc[mf][nf][0], acc[mf][nf][1], acc[mf][nf][2], acc[mf][nf][3],
                             al0, al1, al2, al3, bh[nf][0], bh[nf][1]);
            }
        }
    }

    // ---- epilogue ----
    const int g = lane >> 2;
    const int t = lane & 3;
#pragma unroll
    for (int mf = 0; mf < 4; mf++) {
#pragma unroll
        for (int nf = 0; nf < 4; nf++) {
            const int m_lo = m0 + wm * 64 + mf * 16 + g;
            const int n    = n0 + wn * 32 + nf * 8 + t * 2;
            const float2 bb = *(const float2*)(Bias + n);
            float2 v0, v1;
            v0.x = acc[mf][nf][0] + bb.x; v0.y = acc[mf][nf][1] + bb.y;
            v1.x = acc[mf][nf][2] + bb.x; v1.y = acc[mf][nf][3] + bb.y;
            if (MODE == 0) {
                *(float2*)(OutF + (size_t)m_lo * HID + n)       = v0;
                *(float2*)(OutF + (size_t)(m_lo + 8) * HID + n) = v1;
            } else {
                v0.x *= scale; v0.y *= scale; v1.x *= scale; v1.y *= scale;
                const int h = n >> 7;
                const int d = n & (HDIM - 1);
                const int b0b = m_lo >> 11, s0 = m_lo & (SEQLEN - 1);
                const int b1b = (m_lo + 8) >> 11, s1 = (m_lo + 8) & (SEQLEN - 1);
                const size_t o0 = ((size_t)(b0b * NHEADS + h) * SEQLEN + s0) * HDIM + d;
                const size_t o1 = ((size_t)(b1b * NHEADS + h) * SEQLEN + s1) * HDIM + d;
                __nv_bfloat16 hx, lx, hy, ly;
                split_bf16(v0.x, hx, lx); split_bf16(v0.y, hy, ly);
                *(__nv_bfloat162*)(OutHi + o0) = __nv_bfloat162(hx, hy);
                *(__nv_bfloat162*)(OutLo + o0) = __nv_bfloat162(lx, ly);
                split_bf16(v1.x, hx, lx); split_bf16(v1.y, hy, ly);
                *(__nv_bfloat162*)(OutHi + o1) = __nv_bfloat162(hx, hy);
                *(__nv_bfloat162*)(OutLo + o1) = __nv_bfloat162(lx, ly);
            }
        }
    }
}

__global__ __launch_bounds__(256)
void gemm_qkv_kernel(const float* __restrict__ bq, const float* __restrict__ bk,
                     const float* __restrict__ bv) {
    const int z = blockIdx.z;
    const __nv_bfloat16* Whi = g_whi + (size_t)z * HID * HID;
    const __nv_bfloat16* Wlo = g_wlo + (size_t)z * HID * HID;
    const float* B = (z == 0) ? bq : (z == 1 ? bk : bv);
    __nv_bfloat16* Ohi = (z == 0) ? g_qhi : (z == 1 ? g_khi : g_vhi);
    __nv_bfloat16* Olo = (z == 0) ? g_qlo : (z == 1 ? g_klo : g_vlo);
    const float scale = (z == 0) ? 0.08838834764831845f : 1.0f;
    gemm_body<1>(g_xhi, g_xlo, Whi, Wlo, B, nullptr, Ohi, Olo, scale);
}

__global__ __launch_bounds__(256)
void gemm_out_kernel(const float* __restrict__ bo, float* __restrict__ out) {
    gemm_body<0>(g_ohi, g_olo, g_whi + (size_t)3 * HID * HID,
                 g_wlo + (size_t)3 * HID * HID, bo, out, nullptr, nullptr, 1.0f);
}

// ===================== Flash attention (bf16 mma, P in regs) ===============
// CTA = 128 q-rows of one (b,h); kv tile 64; K/V double-buffered via cp.async.
// Q/K/V pre-split bf16. P in registers (QK C-frag == PV A-frag).
// Smem: Q 68KB + 2 KV stages of 68KB = 204KB -> 1 CTA/SM.
#define AQ 136
#define AT_QHI 0
#define AT_QLO 34816
#define AT_KV0 69632
#define KV_STAGE 69632          // KHI 0 | KLO 17408 | VHI 34816 | VLO 52224
#define KV_KLO 17408
#define KV_VHI 34816
#define KV_VLO 52224
#define AT_SMEM (AT_KV0 + 2 * KV_STAGE)   // 208896

__global__ __launch_bounds__(256, 1)
void attn_mma_kernel() {
    extern __shared__ char sm[];
    const uint32_t sb = smem_u32(sm);
    const int tid  = threadIdx.x;
    const int wid  = tid >> 5;
    const int lane = tid & 31;
    const int qt = blockIdx.x;
    const int bh = blockIdx.y;
    const int q0 = qt * 128;

    const size_t base = (size_t)bh * SEQLEN * HDIM;

    const int lrow = (lane & 7) + ((lane >> 3) & 1) * 8;
    const int lk   = (lane >> 4) * 8;
    const int g    = lane >> 2;
    const int t    = lane & 3;

    // KV loader mapping: row = tid>>2 (0..63), chunks (tid&3)*4 .. +3
    const int krow = tid >> 2;
    const int kc4  = (tid & 3) * 4;
    const uint32_t kv_dst = sb + AT_KV0 + (uint32_t)(krow * 272 + kc4 * 16);
    const size_t   kv_src = base + (size_t)krow * HDIM + kc4 * 8;

    // ---- load Q tile (plain copy, once) ----
    {
        const int row  = tid >> 1;
        const int half = (tid & 1) * 64;
        const __nv_bfloat16* qh = g_qhi + base + (size_t)(q0 + row) * HDIM + half;
        const __nv_bfloat16* ql = g_qlo + base + (size_t)(q0 + row) * HDIM + half;
        char* dh = sm + AT_QHI + (row * AQ + half) * 2;
        char* dl = sm + AT_QLO + (row * AQ + half) * 2;
#pragma unroll
        for (int c = 0; c < 8; c++) {
            *(uint4*)(dh + c * 16) = *(const uint4*)(qh + c * 8);
            *(uint4*)(dl + c * 16) = *(const uint4*)(ql + c * 8);
        }
    }

    // ---- prologue: prefetch KV tile 0 into stage 0 ----
    {
#pragma unroll
        for (int c = 0; c < 4; c++) {
            CP16(kv_dst + c * 16,            g_khi + kv_src + c * 8);
            CP16(kv_dst + KV_KLO + c * 16,   g_klo + kv_src + c * 8);
            CP16(kv_dst + KV_VHI + c * 16,   g_vhi + kv_src + c * 8);
            CP16(kv_dst + KV_VLO + c * 16,   g_vlo + kv_src + c * 8);
        }
        CP_COMMIT();
    }

    float mi0 = -INFINITY, mi1 = -INFINITY, li0 = 0.f, li1 = 0.f;
    float o[16][4];
#pragma unroll
    for (int nf = 0; nf < 16; nf++)
#pragma unroll
        for (int c = 0; c < 4; c++) o[nf][c] = 0.f;

    const int qrow0 = q0 + wid * 16 + g;
    const int qrow1 = qrow0 + 8;
    const int jmax  = 2 * qt + 2;

    const uint32_t aQh = sb + AT_QHI + (uint32_t)(((wid * 16 + lrow) * AQ + lk) * 2);
    const uint32_t aQl = aQh + (AT_QLO - AT_QHI);
    const uint32_t bK0 = sb + AT_KV0 + (uint32_t)((lrow * AQ + lk) * 2);
    const uint32_t bV0 = sb + AT_KV0 + KV_VHI +
        (uint32_t)((((lane & 7) + ((lane >> 3) & 1) * 8) * AQ + ((lane >> 4) & 1) * 8) * 2);

    for (int j = 0; j < jmax; j++) {
        CP_WAIT0();
        __syncthreads();   // KV tile j visible; previous tile's reads done

        // ---- prefetch KV tile j+1 into alternate stage ----
        if (j + 1 < jmax) {
            const uint32_t so = ((j + 1) & 1) * KV_STAGE;
            const size_t  gso = kv_src + (size_t)(j + 1) * 64 * HDIM;
#pragma unroll
            for (int c = 0; c < 4; c++) {
                CP16(kv_dst + so + c * 16,          g_khi + gso + c * 8);
                CP16(kv_dst + so + KV_KLO + c * 16, g_klo + gso + c * 8);
                CP16(kv_dst + so + KV_VHI + c * 16, g_vhi + gso + c * 8);
                CP16(kv_dst + so + KV_VLO + c * 16, g_vlo + gso + c * 8);
            }
        }
        CP_COMMIT();

        const int k0 = j * 64;
        const uint32_t stg = (j & 1) * KV_STAGE;
        const uint32_t bKh = bK0 + stg;
        const uint32_t bKl = bKh + KV_KLO;
        const uint32_t bVt = bV0 + stg;

        // ---- S = Q @ K^T (M=16/warp, N=64, K=128) ----
        float s[8][4];
#pragma unroll
        for (int nf = 0; nf < 8; nf++)
#pragma unroll
            for (int c = 0; c < 4; c++) s[nf][c] = 0.f;

#pragma unroll
        for (int ks = 0; ks < 8; ks++) {
            const uint32_t ko = (uint32_t)(ks * 32);
            uint32_t qh0, qh1, qh2, qh3, ql0, ql1, ql2, ql3;
            LDSM_X4(qh0, qh1, qh2, qh3, aQh + ko);
            LDSM_X4(ql0, ql1, ql2, ql3, aQl + ko);
#pragma unroll
            for (int p = 0; p < 4; p++) {
                const uint32_t po = (uint32_t)(p * 16 * AQ * 2) + ko;
                uint32_t kh0, kh1, kh2, kh3, kl0, kl1, kl2, kl3;
                LDSM_X4(kh0, kh1, kh2, kh3, bKh + po);
                LDSM_X4(kl0, kl1, kl2, kl3, bKl + po);
                // interleaved terms: acc spacing 2
                MMA_BF16(s[2*p][0], s[2*p][1], s[2*p][2], s[2*p][3],
                         qh0, qh1, qh2, qh3, kh0, kh2);
                MMA_BF16(s[2*p+1][0], s[2*p+1][1], s[2*p+1][2], s[2*p+1][3],
                         qh0, qh1, qh2, qh3, kh1, kh3);
                MMA_BF16(s[2*p][0], s[2*p][1], s[2*p][2], s[2*p][3],
                         qh0, qh1, qh2, qh3, kl0, kl2);
                MMA_BF16(s[2*p+1][0], s[2*p+1][1], s[2*p+1][2], s[2*p+1][3],
                         qh0, qh1, qh2, qh3, kl1, kl3);
                MMA_BF16(s[2*p][0], s[2*p][1], s[2*p][2], s[2*p][3],
                         ql0, ql1, ql2, ql3, kh0, kh2);
                MMA_BF16(s[2*p+1][0], s[2*p+1][1], s[2*p+1][2], s[2*p+1][3],
                         ql0, ql1, ql2, ql3, kh1, kh3);
            }
        }

        // ---- causal mask ----
        if (j >= 2 * qt) {
#pragma unroll
            for (int nf = 0; nf < 8; nf++) {
                const int kc = k0 + nf * 8 + t * 2;
                if (kc     > qrow0) s[nf][0] = -INFINITY;
                if (kc + 1 > qrow0) s[nf][1] = -INFINITY;
                if (kc     > qrow1) s[nf][2] = -INFINITY;
                if (kc + 1 > qrow1) s[nf][3] = -INFINITY;
            }
        }

        // ---- online softmax ----
        float rmax0 = -INFINITY, rmax1 = -INFINITY;
#pragma unroll
        for (int nf = 0; nf < 8; nf++) {
            rmax0 = fmaxf(rmax0, fmaxf(s[nf][0], s[nf][1]));
            rmax1 = fmaxf(rmax1, fmaxf(s[nf][2], s[nf][3]));
        }
        rmax0 = fmaxf(rmax0, __shfl_xor_sync(0xffffffffu, rmax0, 1));
        rmax0 = fmaxf(rmax0, __shfl_xor_sync(0xffffffffu, rmax0, 2));
        rmax1 = fmaxf(rmax1, __shfl_xor_sync(0xffffffffu, rmax1, 1));
        rmax1 = fmaxf(rmax1, __shfl_xor_sync(0xffffffffu, rmax1, 2));
        const float mn0 = fmaxf(mi0, rmax0);
        const float mn1 = fmaxf(mi1, rmax1);
        const float corr0 = __expf(mi0 - mn0);
        const float corr1 = __expf(mi1 - mn1);
        mi0 = mn0; mi1 = mn1;

        uint32_t ph[4][4], pl[4][4];
        float rs0 = 0.f, rs1 = 0.f;
#pragma unroll
        for (int nf = 0; nf < 8; nf++) {
            const float p0 = __expf(s[nf][0] - mn0);
            const float p1 = __expf(s[nf][1] - mn0);
            const float p2 = __expf(s[nf][2] - mn1);
            const float p3 = __expf(s[nf][3] - mn1);
            rs0 += p0 + p1;
            rs1 += p2 + p3;
            __nv_bfloat16 h0, l0, h1, l1, h2, l2, h3, l3;
            split_bf16(p0, h0, l0); split_bf16(p1, h1, l1);
            split_bf16(p2, h2, l2); split_bf16(p3, h3, l3);
            const int ks = nf >> 1;
            const int r  = (nf & 1) * 2;
            ph[ks][r]     = packbf(h0, h1);
            ph[ks][r + 1] = packbf(h2, h3);
            pl[ks][r]     = packbf(l0, l1);
            pl[ks][r + 1] = packbf(l2, l3);
        }
        rs0 += __shfl_xor_sync(0xffffffffu, rs0, 1);
        rs0 += __shfl_xor_sync(0xffffffffu, rs0, 2);
        rs1 += __shfl_xor_sync(0xffffffffu, rs1, 1);
        rs1 += __shfl_xor_sync(0xffffffffu, rs1, 2);
        li0 = li0 * corr0 + rs0;
        li1 = li1 * corr1 + rs1;

#pragma unroll
        for (int nf = 0; nf < 16; nf++) {
            o[nf][0] *= corr0; o[nf][1] *= corr0;
            o[nf][2] *= corr1; o[nf][3] *= corr1;
        }

        // ---- O += P @ V (V via ldmatrix.trans; interleaved terms) ----
#pragma unroll
        for (int ks = 0; ks < 4; ks++) {
            const uint32_t kvo = (uint32_t)(ks * 16 * AQ * 2);
#pragma unroll
            for (int p = 0; p < 8; p++) {
                const uint32_t va = bVt + kvo + (uint32_t)(p * 16 * 2);
                uint32_t vh0, vh1, vh2, vh3, vl0, vl1, vl2, vl3;
                LDSM_X4_T(vh0, vh1, vh2, vh3, va);
                LDSM_X4_T(vl0, vl1, vl2, vl3, va + (KV_VLO - KV_VHI));
                MMA_BF16(o[2*p][0], o[2*p][1], o[2*p][2], o[2*p][3],
                         ph[ks][0], ph[ks][1], ph[ks][2], ph[ks][3], vh0, vh1);
                MMA_BF16(o[2*p+1][0], o[2*p+1][1], o[2*p+1][2], o[2*p+1][3],
                         ph[ks][0], ph[ks][1], ph[ks][2], ph[ks][3], vh2, vh3);
                MMA_BF16(o[2*p][0], o[2*p][1], o[2*p][2], o[2*p][3],
                         ph[ks][0], ph[ks][1], ph[ks][2], ph[ks][3], vl0, vl1);
                MMA_BF16(o[2*p+1][0], o[2*p+1][1], o[2*p+1][2], o[2*p+1][3],
                         ph[ks][0], ph[ks][1], ph[ks][2], ph[ks][3], vl2, vl3);
                MMA_BF16(o[2*p][0], o[2*p][1], o[2*p][2], o[2*p][3],
                         pl[ks][0], pl[ks][1], pl[ks][2], pl[ks][3], vh0, vh1);
                MMA_BF16(o[2*p+1][0], o[2*p+1][1], o[2*p+1][2], o[2*p+1][3],
                         pl[ks][0], pl[ks][1], pl[ks][2], pl[ks][3], vh2, vh3);
            }
        }
    }

    // ---- normalize, split, write bf16 hi/lo in [m][HID] ----
    const int b = bh >> 4, h = bh & 15;
    const float inv0 = 1.0f / li0;
    const float inv1 = 1.0f / li1;
    const size_t r0base = ((size_t)b * SEQLEN + qrow0) * HID + h * HDIM;
    const size_t r1base = ((size_t)b * SEQLEN + qrow1) * HID + h * HDIM;
#pragma unroll
    for (int nf = 0; nf < 16; nf++) {
        const int d = nf * 8 + t * 2;
        __nv_bfloat16 hx, lx, hy, ly;
        split_bf16(o[nf][0] * inv0, hx, lx); split_bf16(o[nf][1] * inv0, hy, ly);
        *(__nv_bfloat162*)(g_ohi + r0base + d) = __nv_bfloat162(hx, hy);
        *(__nv_bfloat162*)(g_olo + r0base + d) = __nv_bfloat162(lx, ly);
        split_bf16(o[nf][2] * inv1, hx, lx); split_bf16(o[nf][3] * inv1, hy, ly);
        *(__nv_bfloat162*)(g_ohi + r1base + d) = __nv_bfloat162(hx, hy);
        *(__nv_bfloat162*)(g_olo + r1base + d) = __nv_bfloat162(lx, ly);
    }
}

// ---------------------------------------------------------------------------
extern "C" void kernel_launch(void* const* d_in, const int* in_sizes, int n_in,
                              void* d_out, int out_size) {
    const float* x  = (const float*)d_in[0];
    const float* wq = (const float*)d_in[1];
    const float* wk = (const float*)d_in[2];
    const float* wv = (const float*)d_in[3];
    const float* wo = (const float*)d_in[4];
    const float* bq = (const float*)d_in[5];
    const float* bk = (const float*)d_in[6];
    const float* bv = (const float*)d_in[7];
    const float* bo = (const float*)d_in[8];
    float* out = (float*)d_out;

    cudaFuncSetAttribute(gemm_qkv_kernel,
                         cudaFuncAttributeMaxDynamicSharedMemorySize, GSM_TOTAL);
    cudaFuncSetAttribute(gemm_out_kernel,
                         cudaFuncAttributeMaxDynamicSharedMemorySize, GSM_TOTAL);
    cudaFuncSetAttribute(attn_mma_kernel,
                         cudaFuncAttributeMaxDynamicSharedMemorySize, AT_SMEM);

    __nv_bfloat16 *xhi, *xlo, *whi, *wlo;
    cudaGetSymbolAddress((void**)&xhi, g_xhi);
    cudaGetSymbolAddress((void**)&xlo, g_xlo);
    cudaGetSymbolAddress((void**)&whi, g_whi);
    cudaGetSymbolAddress((void**)&wlo, g_wlo);

    // 0) one-time fp32 -> bf16 hi/lo splits
    const int nx = MTOT * HID, nw = HID * HID;
    split_f32_kernel<<<nx / 1024, 256>>>(x, xhi, xlo, nx);
    split_f32_kernel<<<nw / 1024, 256>>>(wq, whi + 0 * (size_t)nw, wlo + 0 * (size_t)nw, nw);
    split_f32_kernel<<<nw / 1024, 256>>>(wk, whi + 1 * (size_t)nw, wlo + 1 * (size_t)nw, nw);
    split_f32_kernel<<<nw / 1024, 256>>>(wv, whi + 2 * (size_t)nw, wlo + 2 * (size_t)nw, nw);
    split_f32_kernel<<<nw / 1024, 256>>>(wo, whi + 3 * (size_t)nw, wlo + 3 * (size_t)nw, nw);

    // 1) QKV projections (3-stage pipelined bf16 GEMM, chain-free MMA order)
    gemm_qkv_kernel<<<dim3(HID / 128, MTOT / 128, 3), 256, GSM_TOTAL>>>(bq, bk, bv);
    // 2) Causal flash attention (kv=64, double-buffered cp.async K/V)
    attn_mma_kernel<<<dim3(SEQLEN / 128, BATCHSZ * NHEADS), 256, AT_SMEM>>>();
    // 3) Output projection (fp32 out)
    gemm_out_kernel<<<dim3(HID / 128, MTOT / 128), 256, GSM_TOTAL>>>(bo, out);
}

// round 9
// speedup vs baseline: 1.1056x; 1.1056x over previous
#include <cuda_runtime.h>
#include <cuda_bf16.h>
#include <math.h>
#include <cstdint>
#include <string.h>

#define HID     2048
#define NHEADS  16
#define HDIM    128
#define BATCHSZ 2
#define SEQLEN  2048
#define MTOT    (BATCHSZ * SEQLEN)   // 4096

// ---------------- scratch (allocation-free), all bf16 split pairs ----------
__device__ __nv_bfloat16 g_xhi[MTOT * HID],  g_xlo[MTOT * HID];
__device__ __nv_bfloat16 g_whi[4 * HID * HID], g_wlo[4 * HID * HID];
__device__ __nv_bfloat16 g_qhi[MTOT * HID],  g_qlo[MTOT * HID];
__device__ __nv_bfloat16 g_khi[MTOT * HID],  g_klo[MTOT * HID];
__device__ __nv_bfloat16 g_vhi[MTOT * HID],  g_vlo[MTOT * HID];
__device__ __nv_bfloat16 g_ohi[MTOT * HID],  g_olo[MTOT * HID];

// ============================ helpers ======================================
__device__ __forceinline__ uint32_t smem_u32(const void* p) {
    uint32_t a;
    asm("{ .reg .u64 t; cvta.to.shared.u64 t, %1; cvt.u32.u64 %0, t; }"
        : "=r"(a) : "l"(p));
    return a;
}

#define LDSM_X4(r0, r1, r2, r3, addr)                                    \
    asm volatile("ldmatrix.sync.aligned.m8n8.x4.shared.b16 "             \
                 "{%0,%1,%2,%3}, [%4];"                                  \
                 : "=r"(r0), "=r"(r1), "=r"(r2), "=r"(r3) : "r"(addr))

#define LDSM_X4_T(r0, r1, r2, r3, addr)                                  \
    asm volatile("ldmatrix.sync.aligned.m8n8.x4.trans.shared.b16 "       \
                 "{%0,%1,%2,%3}, [%4];"                                  \
                 : "=r"(r0), "=r"(r1), "=r"(r2), "=r"(r3) : "r"(addr))

#define MMA_BF16(c0, c1, c2, c3, a0, a1, a2, a3, b0, b1)                 \
    asm volatile("mma.sync.aligned.m16n8k16.row.col.f32.bf16.bf16.f32 "  \
                 "{%0,%1,%2,%3}, {%4,%5,%6,%7}, {%8,%9}, {%0,%1,%2,%3};" \
                 : "+f"(c0), "+f"(c1), "+f"(c2), "+f"(c3)                \
                 : "r"(a0), "r"(a1), "r"(a2), "r"(a3), "r"(b0), "r"(b1))

#define CP16(saddr, gptr)                                                \
    asm volatile("cp.async.cg.shared.global [%0], [%1], 16;"             \
                 :: "r"(saddr), "l"(gptr))
#define CP_COMMIT() asm volatile("cp.async.commit_group;" ::: "memory")
#define CP_WAIT0()  asm volatile("cp.async.wait_group 0;" ::: "memory")

__device__ __forceinline__ void split_bf16(float x, __nv_bfloat16& hi, __nv_bfloat16& lo) {
    hi = __float2bfloat16_rn(x);
    lo = __float2bfloat16_rn(x - __bfloat162float(hi));
}
__device__ __forceinline__ uint32_t packbf(__nv_bfloat16 a, __nv_bfloat16 b) {
    __nv_bfloat162 t; t.x = a; t.y = b;
    uint32_t u; memcpy(&u, &t, 4);
    return u;
}

// ======================= split kernels (one-time) ==========================
__global__ __launch_bounds__(256)
void split_f32_kernel(const float* __restrict__ src,
                      __nv_bfloat16* __restrict__ hi,
                      __nv_bfloat16* __restrict__ lo, int n) {
    const int i = (blockIdx.x * 256 + threadIdx.x) * 4;
    if (i >= n) return;
    float4 v = *(const float4*)(src + i);
    __nv_bfloat16 hx, lx, hy, ly;
    split_bf16(v.x, hx, lx); split_bf16(v.y, hy, ly);
    *(__nv_bfloat162*)(hi + i) = __nv_bfloat162(hx, hy);
    *(__nv_bfloat162*)(lo + i) = __nv_bfloat162(lx, ly);
    split_bf16(v.z, hx, lx); split_bf16(v.w, hy, ly);
    *(__nv_bfloat162*)(hi + i + 2) = __nv_bfloat162(hx, hy);
    *(__nv_bfloat162*)(lo + i + 2) = __nv_bfloat162(lx, ly);
}

// ================= pipelined bf16-split GEMM (cp.async) ====================
// C[M=4096, N=2048] = A @ W^T + bias, pre-split bf16 inputs.
// CTA 128x128, 256 threads = 8 warps (2M x 4N), warp tile 64x32.
// K chunk 32. 2-stage cp.async. TERM-MAJOR mma order (hh over nf, then hl,
// then lh) -> dependent-accumulator spacing 4 instead of 1.
#define KSTRIDE 40
#define TILE_B  (128 * KSTRIDE * 2)      // 10240 B
#define STAGE_B (4 * TILE_B)             // 40960 B
#define GSM_TOTAL (2 * STAGE_B)          // 81920 B
#define NKC (HID / 32)                   // 64

// MODE 0: fp32 Out[m*HID+n].  MODE 1: bf16 split OutHi/OutLo [b,h,s,d] * scale
template <int MODE>
__device__ __forceinline__ void gemm_body(const __nv_bfloat16* __restrict__ Ahi,
                                          const __nv_bfloat16* __restrict__ Alo,
                                          const __nv_bfloat16* __restrict__ Whi,
                                          const __nv_bfloat16* __restrict__ Wlo,
                                          const float* __restrict__ Bias,
                                          float* __restrict__ OutF,
                                          __nv_bfloat16* __restrict__ OutHi,
                                          __nv_bfloat16* __restrict__ OutLo,
                                          float scale) {
    extern __shared__ char sm[];
    const uint32_t sb = smem_u32(sm);
    const int tid  = threadIdx.x;
    const int wid  = tid >> 5;
    const int lane = tid & 31;
    const int m0 = blockIdx.y * 128;
    const int n0 = blockIdx.x * 128;
    const int wm = wid & 1;
    const int wn = wid >> 1;

    const int lrow = (lane & 7) + ((lane >> 3) & 1) * 8;
    const int lk   = (lane >> 4) * 8;

    const int r0 = tid >> 2;                 // 0..63
    const int c0 = (tid & 3) * 8;            // bf16 col 0,8,16,24
    const __nv_bfloat16* gA[4];
    gA[0] = Ahi + (size_t)(m0 + r0) * HID + c0;
    gA[1] = Alo + (size_t)(m0 + r0) * HID + c0;
    gA[2] = Whi + (size_t)(n0 + r0) * HID + c0;
    gA[3] = Wlo + (size_t)(n0 + r0) * HID + c0;
    const uint32_t sA0 = sb + (uint32_t)(r0 * 80 + (tid & 3) * 16);
    const uint32_t sA1 = sA0 + 64 * 80;

    float acc[4][4][4];
#pragma unroll
    for (int i = 0; i < 4; i++)
#pragma unroll
        for (int j = 0; j < 4; j++)
#pragma unroll
            for (int c = 0; c < 4; c++) acc[i][j][c] = 0.f;

    // ---- prologue: stage 0 ----
#pragma unroll
    for (int t = 0; t < 4; t++) {
        CP16(sA0 + t * TILE_B, gA[t]);
        CP16(sA1 + t * TILE_B, gA[t] + (size_t)64 * HID);
    }
    CP_COMMIT();

    for (int kc = 0; kc < NKC; kc++) {
        CP_WAIT0();
        __syncthreads();
        if (kc + 1 < NKC) {
            const uint32_t soff = ((kc + 1) & 1) * STAGE_B;
            const int go = (kc + 1) * 32;
#pragma unroll
            for (int t = 0; t < 4; t++) {
                CP16(sA0 + soff + t * TILE_B, gA[t] + go);
                CP16(sA1 + soff + t * TILE_B, gA[t] + (size_t)64 * HID + go);
            }
            CP_COMMIT();
        }

        const uint32_t stg = (kc & 1) * STAGE_B;
        const uint32_t aH = sb + stg + (uint32_t)(((wm * 64 + lrow) * KSTRIDE + lk) * 2);
        const uint32_t bH = sb + stg + 2 * TILE_B +
                            (uint32_t)(((wn * 32 + lrow) * KSTRIDE + lk) * 2);
#pragma unroll
        for (int ks = 0; ks < 2; ks++) {
            const uint32_t ko = (uint32_t)(ks * 32);
            uint32_t bh[4][2], bl[4][2];
#pragma unroll
            for (int p = 0; p < 2; p++) {
                const uint32_t ba = bH + (uint32_t)(p * 16 * KSTRIDE * 2) + ko;
                uint32_t q0, q1, q2, q3;
                LDSM_X4(q0, q1, q2, q3, ba);
                bh[2 * p][0] = q0; bh[2 * p][1] = q2;
                bh[2 * p + 1][0] = q1; bh[2 * p + 1][1] = q3;
                LDSM_X4(q0, q1, q2, q3, ba + TILE_B);
                bl[2 * p][0] = q0; bl[2 * p][1] = q2;
                bl[2 * p + 1][0] = q1; bl[2 * p + 1][1] = q3;
            }
#pragma unroll
            for (int mf = 0; mf < 4; mf++) {
                const uint32_t aa = aH + (uint32_t)(mf * 16 * KSTRIDE * 2) + ko;
                uint32_t ah0, ah1, ah2, ah3, al0, al1, al2, al3;
                LDSM_X4(ah0, ah1, ah2, ah3, aa);
                LDSM_X4(al0, al1, al2, al3, aa + TILE_B);
                // TERM-MAJOR: all nf for hh, then hl, then lh (acc spacing 4)
#pragma unroll
                for (int nf = 0; nf < 4; nf++)
                    MMA_BF16(acc[mf][nf][0], acc[mf][nf][1], acc[mf][nf][2], acc[mf][nf][3],
                             ah0, ah1, ah2, ah3, bh[nf][0], bh[nf][1]);
#pragma unroll
                for (int nf = 0; nf < 4; nf++)
                    MMA_BF16(acc[mf][nf][0], acc[mf][nf][1], acc[mf][nf][2], acc[mf][nf][3],
                             ah0, ah1, ah2, ah3, bl[nf][0], bl[nf][1]);
#pragma unroll
                for (int nf = 0; nf < 4; nf++)
                    MMA_BF16(acc[mf][nf][0], acc[mf][nf][1], acc[mf][nf][2], acc[mf][nf][3],
                             al0, al1, al2, al3, bh[nf][0], bh[nf][1]);
            }
        }
    }

    // ---- epilogue ----
    const int g = lane >> 2;
    const int t = lane & 3;
#pragma unroll
    for (int mf = 0; mf < 4; mf++) {
#pragma unroll
        for (int nf = 0; nf < 4; nf++) {
            const int m_lo = m0 + wm * 64 + mf * 16 + g;
            const int n    = n0 + wn * 32 + nf * 8 + t * 2;
            const float2 bb = *(const float2*)(Bias + n);
            float2 v0, v1;
            v0.x = acc[mf][nf][0] + bb.x; v0.y = acc[mf][nf][1] + bb.y;
            v1.x = acc[mf][nf][2] + bb.x; v1.y = acc[mf][nf][3] + bb.y;
            if (MODE == 0) {
                *(float2*)(OutF + (size_t)m_lo * HID + n)       = v0;
                *(float2*)(OutF + (size_t)(m_lo + 8) * HID + n) = v1;
            } else {
                v0.x *= scale; v0.y *= scale; v1.x *= scale; v1.y *= scale;
                const int h = n >> 7;
                const int d = n & (HDIM - 1);
                const int b0b = m_lo >> 11, s0 = m_lo & (SEQLEN - 1);
                const int b1b = (m_lo + 8) >> 11, s1 = (m_lo + 8) & (SEQLEN - 1);
                const size_t o0 = ((size_t)(b0b * NHEADS + h) * SEQLEN + s0) * HDIM + d;
                const size_t o1 = ((size_t)(b1b * NHEADS + h) * SEQLEN + s1) * HDIM + d;
                __nv_bfloat16 hx, lx, hy, ly;
                split_bf16(v0.x, hx, lx); split_bf16(v0.y, hy, ly);
                *(__nv_bfloat162*)(OutHi + o0) = __nv_bfloat162(hx, hy);
                *(__nv_bfloat162*)(OutLo + o0) = __nv_bfloat162(lx, ly);
                split_bf16(v1.x, hx, lx); split_bf16(v1.y, hy, ly);
                *(__nv_bfloat162*)(OutHi + o1) = __nv_bfloat162(hx, hy);
                *(__nv_bfloat162*)(OutLo + o1) = __nv_bfloat162(lx, ly);
            }
        }
    }
}

__global__ __launch_bounds__(256, 2)
void gemm_qkv_kernel(const float* __restrict__ bq, const float* __restrict__ bk,
                     const float* __restrict__ bv) {
    const int z = blockIdx.z;
    const __nv_bfloat16* Whi = g_whi + (size_t)z * HID * HID;
    const __nv_bfloat16* Wlo = g_wlo + (size_t)z * HID * HID;
    const float* B = (z == 0) ? bq : (z == 1 ? bk : bv);
    __nv_bfloat16* Ohi = (z == 0) ? g_qhi : (z == 1 ? g_khi : g_vhi);
    __nv_bfloat16* Olo = (z == 0) ? g_qlo : (z == 1 ? g_klo : g_vlo);
    const float scale = (z == 0) ? 0.08838834764831845f : 1.0f;
    gemm_body<1>(g_xhi, g_xlo, Whi, Wlo, B, nullptr, Ohi, Olo, scale);
}

__global__ __launch_bounds__(256, 2)
void gemm_out_kernel(const float* __restrict__ bo, float* __restrict__ out) {
    gemm_body<0>(g_ohi, g_olo, g_whi + (size_t)3 * HID * HID,
                 g_wlo + (size_t)3 * HID * HID, bo, out, nullptr, nullptr, 1.0f);
}

// ===================== Flash attention (bf16 mma, P in regs) ===============
// EXACT R6 version (best passing): CTA = 128 q-rows of one (b,h); kv tile 64.
// Q/K/V pre-split bf16 (pure copies). P in registers. V via ldmatrix.trans.
#define AQ 136
#define AT_QHI 0
#define AT_QLO 34816
#define AT_KHI 69632
#define AT_KLO 87040
#define AT_VHI 104448
#define AT_VLO 121856
#define AT_SMEM 139264

__global__ __launch_bounds__(256, 1)
void attn_mma_kernel() {
    extern __shared__ char sm[];
    const uint32_t sb = smem_u32(sm);
    const int tid  = threadIdx.x;
    const int wid  = tid >> 5;
    const int lane = tid & 31;
    const int qt = blockIdx.x;
    const int bh = blockIdx.y;
    const int q0 = qt * 128;

    const size_t base = (size_t)bh * SEQLEN * HDIM;

    const int lrow = (lane & 7) + ((lane >> 3) & 1) * 8;
    const int lk   = (lane >> 4) * 8;
    const int g    = lane >> 2;
    const int t    = lane & 3;

    // ---- load Q tile (pure copy) ----
    {
        const int row  = tid >> 1;
        const int half = (tid & 1) * 64;
        const __nv_bfloat16* qh = g_qhi + base + (size_t)(q0 + row) * HDIM + half;
        const __nv_bfloat16* ql = g_qlo + base + (size_t)(q0 + row) * HDIM + half;
        char* dh = sm + AT_QHI + (row * AQ + half) * 2;
        char* dl = sm + AT_QLO + (row * AQ + half) * 2;
#pragma unroll
        for (int c = 0; c < 8; c++) {
            *(uint4*)(dh + c * 16) = *(const uint4*)(qh + c * 8);
            *(uint4*)(dl + c * 16) = *(const uint4*)(ql + c * 8);
        }
    }

    float mi0 = -INFINITY, mi1 = -INFINITY, li0 = 0.f, li1 = 0.f;
    float o[16][4];
#pragma unroll
    for (int nf = 0; nf < 16; nf++)
#pragma unroll
        for (int c = 0; c < 4; c++) o[nf][c] = 0.f;

    const int qrow0 = q0 + wid * 16 + g;
    const int qrow1 = qrow0 + 8;
    const int jmax  = 2 * qt + 2;

    const uint32_t aQh = sb + AT_QHI + (uint32_t)(((wid * 16 + lrow) * AQ + lk) * 2);
    const uint32_t aQl = aQh + (AT_QLO - AT_QHI);
    const uint32_t bKh = sb + AT_KHI + (uint32_t)((lrow * AQ + lk) * 2);
    const uint32_t bKl = bKh + (AT_KLO - AT_KHI);
    const uint32_t bVt = sb + AT_VHI +
        (uint32_t)((((lane & 7) + ((lane >> 3) & 1) * 8) * AQ + ((lane >> 4) & 1) * 8) * 2);

    for (int j = 0; j < jmax; j++) {
        const int k0 = j * 64;
        __syncthreads();   // previous PV reads of K/V done

        // ---- load K/V tiles (pure copies) ----
        {
            const int row = tid >> 2;
            const int qtr = (tid & 3) * 32;
            const size_t gsrc = base + (size_t)(k0 + row) * HDIM + qtr;
            const int doff = (row * AQ + qtr) * 2;
#pragma unroll
            for (int c = 0; c < 4; c++) {
                *(uint4*)(sm + AT_KHI + doff + c * 16) = *(const uint4*)(g_khi + gsrc + c * 8);
                *(uint4*)(sm + AT_KLO + doff + c * 16) = *(const uint4*)(g_klo + gsrc + c * 8);
                *(uint4*)(sm + AT_VHI + doff + c * 16) = *(const uint4*)(g_vhi + gsrc + c * 8);
                *(uint4*)(sm + AT_VLO + doff + c * 16) = *(const uint4*)(g_vlo + gsrc + c * 8);
            }
        }
        __syncthreads();

        // ---- S = Q @ K^T ----
        float s[8][4];
#pragma unroll
        for (int nf = 0; nf < 8; nf++)
#pragma unroll
            for (int c = 0; c < 4; c++) s[nf][c] = 0.f;

#pragma unroll
        for (int ks = 0; ks < 8; ks++) {
            const uint32_t ko = (uint32_t)(ks * 32);
            uint32_t qh0, qh1, qh2, qh3, ql0, ql1, ql2, ql3;
            LDSM_X4(qh0, qh1, qh2, qh3, aQh + ko);
            LDSM_X4(ql0, ql1, ql2, ql3, aQl + ko);
#pragma unroll
            for (int p = 0; p < 4; p++) {
                const uint32_t po = (uint32_t)(p * 16 * AQ * 2) + ko;
                uint32_t kh0, kh1, kh2, kh3, kl0, kl1, kl2, kl3;
                LDSM_X4(kh0, kh1, kh2, kh3, bKh + po);
                LDSM_X4(kl0, kl1, kl2, kl3, bKl + po);
                MMA_BF16(s[2*p][0], s[2*p][1], s[2*p][2], s[2*p][3],
                         qh0, qh1, qh2, qh3, kh0, kh2);
                MMA_BF16(s[2*p][0], s[2*p][1], s[2*p][2], s[2*p][3],
                         qh0, qh1, qh2, qh3, kl0, kl2);
                MMA_BF16(s[2*p][0], s[2*p][1], s[2*p][2], s[2*p][3],
                         ql0, ql1, ql2, ql3, kh0, kh2);
                MMA_BF16(s[2*p+1][0], s[2*p+1][1], s[2*p+1][2], s[2*p+1][3],
                         qh0, qh1, qh2, qh3, kh1, kh3);
                MMA_BF16(s[2*p+1][0], s[2*p+1][1], s[2*p+1][2], s[2*p+1][3],
                         qh0, qh1, qh2, qh3, kl1, kl3);
                MMA_BF16(s[2*p+1][0], s[2*p+1][1], s[2*p+1][2], s[2*p+1][3],
                         ql0, ql1, ql2, ql3, kh1, kh3);
            }
        }

        // ---- causal mask ----
        if (j >= 2 * qt) {
#pragma unroll
            for (int nf = 0; nf < 8; nf++) {
                const int kc = k0 + nf * 8 + t * 2;
                if (kc     > qrow0) s[nf][0] = -INFINITY;
                if (kc + 1 > qrow0) s[nf][1] = -INFINITY;
                if (kc     > qrow1) s[nf][2] = -INFINITY;
                if (kc + 1 > qrow1) s[nf][3] = -INFINITY;
            }
        }

        // ---- online softmax + pack P into PV A-fragments ----
        float rmax0 = -INFINITY, rmax1 = -INFINITY;
#pragma unroll
        for (int nf = 0; nf < 8; nf++) {
            rmax0 = fmaxf(rmax0, fmaxf(s[nf][0], s[nf][1]));
            rmax1 = fmaxf(rmax1, fmaxf(s[nf][2], s[nf][3]));
        }
        rmax0 = fmaxf(rmax0, __shfl_xor_sync(0xffffffffu, rmax0, 1));
        rmax0 = fmaxf(rmax0, __shfl_xor_sync(0xffffffffu, rmax0, 2));
        rmax1 = fmaxf(rmax1, __shfl_xor_sync(0xffffffffu, rmax1, 1));
        rmax1 = fmaxf(rmax1, __shfl_xor_sync(0xffffffffu, rmax1, 2));
        const float mn0 = fmaxf(mi0, rmax0);
        const float mn1 = fmaxf(mi1, rmax1);
        const float corr0 = __expf(mi0 - mn0);
        const float corr1 = __expf(mi1 - mn1);
        mi0 = mn0; mi1 = mn1;

        uint32_t ph[4][4], pl[4][4];
        float rs0 = 0.f, rs1 = 0.f;
#pragma unroll
        for (int nf = 0; nf < 8; nf++) {
            const float p0 = __expf(s[nf][0] - mn0);
            const float p1 = __expf(s[nf][1] - mn0);
            const float p2 = __expf(s[nf][2] - mn1);
            const float p3 = __expf(s[nf][3] - mn1);
            rs0 += p0 + p1;
            rs1 += p2 + p3;
            __nv_bfloat16 h0, l0, h1, l1, h2, l2, h3, l3;
            split_bf16(p0, h0, l0); split_bf16(p1, h1, l1);
            split_bf16(p2, h2, l2); split_bf16(p3, h3, l3);
            const int ks = nf >> 1;
            const int r  = (nf & 1) * 2;
            ph[ks][r]     = packbf(h0, h1);
            ph[ks][r + 1] = packbf(h2, h3);
            pl[ks][r]     = packbf(l0, l1);
            pl[ks][r + 1] = packbf(l2, l3);
        }
        rs0 += __shfl_xor_sync(0xffffffffu, rs0, 1);
        rs0 += __shfl_xor_sync(0xffffffffu, rs0, 2);
        rs1 += __shfl_xor_sync(0xffffffffu, rs1, 1);
        rs1 += __shfl_xor_sync(0xffffffffu, rs1, 2);
        li0 = li0 * corr0 + rs0;
        li1 = li1 * corr1 + rs1;

#pragma unroll
        for (int nf = 0; nf < 16; nf++) {
            o[nf][0] *= corr0; o[nf][1] *= corr0;
            o[nf][2] *= corr1; o[nf][3] *= corr1;
        }

        // ---- O += P @ V (V via ldmatrix.trans) ----
#pragma unroll
        for (int ks = 0; ks < 4; ks++) {
            const uint32_t kvo = (uint32_t)(ks * 16 * AQ * 2);
#pragma unroll
            for (int p = 0; p < 8; p++) {
                const uint32_t va = bVt + kvo + (uint32_t)(p * 16 * 2);
                uint32_t vh0, vh1, vh2, vh3, vl0, vl1, vl2, vl3;
                LDSM_X4_T(vh0, vh1, vh2, vh3, va);
                LDSM_X4_T(vl0, vl1, vl2, vl3, va + (AT_VLO - AT_VHI));
                MMA_BF16(o[2*p][0], o[2*p][1], o[2*p][2], o[2*p][3],
                         ph[ks][0], ph[ks][1], ph[ks][2], ph[ks][3], vh0, vh1);
                MMA_BF16(o[2*p][0], o[2*p][1], o[2*p][2], o[2*p][3],
                         ph[ks][0], ph[ks][1], ph[ks][2], ph[ks][3], vl0, vl1);
                MMA_BF16(o[2*p][0], o[2*p][1], o[2*p][2], o[2*p][3],
                         pl[ks][0], pl[ks][1], pl[ks][2], pl[ks][3], vh0, vh1);
                MMA_BF16(o[2*p+1][0], o[2*p+1][1], o[2*p+1][2], o[2*p+1][3],
                         ph[ks][0], ph[ks][1], ph[ks][2], ph[ks][3], vh2, vh3);
                MMA_BF16(o[2*p+1][0], o[2*p+1][1], o[2*p+1][2], o[2*p+1][3],
                         ph[ks][0], ph[ks][1], ph[ks][2], ph[ks][3], vl2, vl3);
                MMA_BF16(o[2*p+1][0], o[2*p+1][1], o[2*p+1][2], o[2*p+1][3],
                         pl[ks][0], pl[ks][1], pl[ks][2], pl[ks][3], vh2, vh3);
            }
        }
    }

    // ---- normalize, split, write bf16 hi/lo in [m][HID] ----
    const int b = bh >> 4, h = bh & 15;
    const float inv0 = 1.0f / li0;
    const float inv1 = 1.0f / li1;
    const size_t r0base = ((size_t)b * SEQLEN + qrow0) * HID + h * HDIM;
    const size_t r1base = ((size_t)b * SEQLEN + qrow1) * HID + h * HDIM;
#pragma unroll
    for (int nf = 0; nf < 16; nf++) {
        const int d = nf * 8 + t * 2;
        __nv_bfloat16 hx, lx, hy, ly;
        split_bf16(o[nf][0] * inv0, hx, lx); split_bf16(o[nf][1] * inv0, hy, ly);
        *(__nv_bfloat162*)(g_ohi + r0base + d) = __nv_bfloat162(hx, hy);
        *(__nv_bfloat162*)(g_olo + r0base + d) = __nv_bfloat162(lx, ly);
        split_bf16(o[nf][2] * inv1, hx, lx); split_bf16(o[nf][3] * inv1, hy, ly);
        *(__nv_bfloat162*)(g_ohi + r1base + d) = __nv_bfloat162(hx, hy);
        *(__nv_bfloat162*)(g_olo + r1base + d) = __nv_bfloat162(lx, ly);
    }
}

// ---------------------------------------------------------------------------
extern "C" void kernel_launch(void* const* d_in, const int* in_sizes, int n_in,
                              void* d_out, int out_size) {
    const float* x  = (const float*)d_in[0];
    const float* wq = (const float*)d_in[1];
    const float* wk = (const float*)d_in[2];
    const float* wv = (const float*)d_in[3];
    const float* wo = (const float*)d_in[4];
    const float* bq = (const float*)d_in[5];
    const float* bk = (const float*)d_in[6];
    const float* bv = (const float*)d_in[7];
    const float* bo = (const float*)d_in[8];
    float* out = (float*)d_out;

    cudaFuncSetAttribute(gemm_qkv_kernel,
                         cudaFuncAttributeMaxDynamicSharedMemorySize, GSM_TOTAL);
    cudaFuncSetAttribute(gemm_out_kernel,
                         cudaFuncAttributeMaxDynamicSharedMemorySize, GSM_TOTAL);
    cudaFuncSetAttribute(attn_mma_kernel,
                         cudaFuncAttributeMaxDynamicSharedMemorySize, AT_SMEM);

    __nv_bfloat16 *xhi, *xlo, *whi, *wlo;
    cudaGetSymbolAddress((void**)&xhi, g_xhi);
    cudaGetSymbolAddress((void**)&xlo, g_xlo);
    cudaGetSymbolAddress((void**)&whi, g_whi);
    cudaGetSymbolAddress((void**)&wlo, g_wlo);

    // 0) one-time fp32 -> bf16 hi/lo splits
    const int nx = MTOT * HID, nw = HID * HID;
    split_f32_kernel<<<nx / 1024, 256>>>(x, xhi, xlo, nx);
    split_f32_kernel<<<nw / 1024, 256>>>(wq, whi + 0 * (size_t)nw, wlo + 0 * (size_t)nw, nw);
    split_f32_kernel<<<nw / 1024, 256>>>(wk, whi + 1 * (size_t)nw, wlo + 1 * (size_t)nw, nw);
    split_f32_kernel<<<nw / 1024, 256>>>(wv, whi + 2 * (size_t)nw, wlo + 2 * (size_t)nw, nw);
    split_f32_kernel<<<nw / 1024, 256>>>(wo, whi + 3 * (size_t)nw, wlo + 3 * (size_t)nw, nw);

    // 1) QKV projections (2-stage pipelined bf16 GEMM, term-major MMA order)
    gemm_qkv_kernel<<<dim3(HID / 128, MTOT / 128, 3), 256, GSM_TOTAL>>>(bq, bk, bv);
    // 2) Causal flash attention (R6 exact)
    attn_mma_kernel<<<dim3(SEQLEN / 128, BATCHSZ * NHEADS), 256, AT_SMEM>>>();
    // 3) Output projection (fp32 out)
    gemm_out_kernel<<<dim3(HID / 128, MTOT / 128), 256, GSM_TOTAL>>>(bo, out);
}